// round 1
// baseline (speedup 1.0000x reference)
#include <cuda_runtime.h>
#include <math.h>

#define H_ 128
#define T_ 28
#define I_ 28
#define C_ 10
#define B_ 8192

// Global scratch for layer-0 input GEMM results (biases folded in): [B][T][H]
__device__ float g_xw0[(size_t)B_ * T_ * H_];

__device__ __forceinline__ float tanh_fast(float x) {
    // tanh(x) = sign(x) * (1 - e) / (1 + e),  e = exp(-2|x|)
    float ax = fabsf(x);
    float e  = __expf(-2.0f * ax);
    float r  = __fdividef(1.0f - e, 1.0f + e);
    return copysignf(r, x);
}

// ---------------------------------------------------------------------------
// Kernel 1: xw0[b][t][j] = sum_d x[b][t][d] * W_ih0[j][d] + b_ih0[j] + b_hh0[j]
// Rows = B*T = 229376. Tile: 64 rows x 128 j per block, 256 threads.
// ---------------------------------------------------------------------------
__global__ void __launch_bounds__(256) xw0_kernel(
    const float* __restrict__ x, const float* __restrict__ Wih0,
    const float* __restrict__ bih0, const float* __restrict__ bhh0)
{
    __shared__ float Wt[I_ * 129];   // Wt[d*129 + j] (pad 129 -> conflict-free STS)
    __shared__ float xs[64 * I_];
    __shared__ float bsum[H_];

    const int tid = threadIdx.x, lane = tid & 31, warp = tid >> 5;

    for (int i = tid; i < H_ * I_; i += 256) {
        int j = i / I_, d = i % I_;           // coalesced LDG (i linear)
        Wt[d * 129 + j] = Wih0[i];
    }
    for (int i = tid; i < H_; i += 256) bsum[i] = bih0[i] + bhh0[i];

    const int row0 = blockIdx.x * 64;
    const float* xr = x + (size_t)row0 * I_;
    for (int i = tid; i < 64 * I_; i += 256) xs[i] = xr[i];
    __syncthreads();

    float bj[4];
#pragma unroll
    for (int m = 0; m < 4; m++) bj[m] = bsum[lane + 32 * m];

    float acc[4][8];
#pragma unroll
    for (int m = 0; m < 4; m++)
#pragma unroll
        for (int r = 0; r < 8; r++) acc[m][r] = bj[m];

    const int rbase = warp * 8;
#pragma unroll
    for (int d = 0; d < I_; d++) {
        float w[4];
#pragma unroll
        for (int m = 0; m < 4; m++) w[m] = Wt[d * 129 + lane + 32 * m];
#pragma unroll
        for (int r = 0; r < 8; r++) {
            float xv = xs[(rbase + r) * I_ + d];
#pragma unroll
            for (int m = 0; m < 4; m++) acc[m][r] = fmaf(w[m], xv, acc[m][r]);
        }
    }

    float* outp = g_xw0 + (size_t)(row0 + rbase) * H_;
#pragma unroll
    for (int r = 0; r < 8; r++)
#pragma unroll
        for (int m = 0; m < 4; m++)
            outp[(size_t)r * H_ + lane + 32 * m] = acc[m][r];
}

// ---------------------------------------------------------------------------
// Kernel 2: fused 2-layer recurrence + FC.
// 256 CTAs x 256 threads. CTA tile = 32 sequences; warp owns 4 sequences
// (h rows warp-private -> no block-level sync in the time loop).
// Smem: Whh0^T, Wih1^T, Whh1^T (k-major, stride 128) + h0/h1 tiles.
// ---------------------------------------------------------------------------
#define SM_W0 0
#define SM_W1 (H_ * H_)
#define SM_W2 (2 * H_ * H_)
#define SM_H0 (3 * H_ * H_)
#define SM_H1 (3 * H_ * H_ + 32 * H_)
#define SM_FLOATS (3 * H_ * H_ + 2 * 32 * H_)   // 57344 floats = 229376 B

extern __shared__ float sm[];

__device__ __forceinline__ void matvec_acc4x4(const float* __restrict__ Wt,
                                              const float* __restrict__ h,
                                              int lane, float (&acc)[4][4])
{
#pragma unroll 4
    for (int k4 = 0; k4 < 32; k4++) {
        float4 hv[4];
#pragma unroll
        for (int r = 0; r < 4; r++)
            hv[r] = *reinterpret_cast<const float4*>(h + r * H_ + k4 * 4);
#pragma unroll
        for (int kk = 0; kk < 4; kk++) {
            float w[4];
            const float* wr = Wt + (k4 * 4 + kk) * H_ + lane;
#pragma unroll
            for (int m = 0; m < 4; m++) w[m] = wr[32 * m];
#pragma unroll
            for (int r = 0; r < 4; r++) {
                float hval = (kk == 0) ? hv[r].x : (kk == 1) ? hv[r].y
                           : (kk == 2) ? hv[r].z : hv[r].w;
#pragma unroll
                for (int m = 0; m < 4; m++)
                    acc[m][r] = fmaf(w[m], hval, acc[m][r]);
            }
        }
    }
}

__global__ void __launch_bounds__(256, 1) rnn_kernel(
    const float* __restrict__ Whh0, const float* __restrict__ Wih1,
    const float* __restrict__ Whh1, const float* __restrict__ bih1,
    const float* __restrict__ bhh1, const float* __restrict__ fcw,
    const float* __restrict__ fcb, float* __restrict__ out)
{
    const int tid = threadIdx.x, lane = tid & 31, warp = tid >> 5;

    // Load weights transposed (k-major). LDG coalesced; STS 32-way conflicts
    // but it's a one-time ~1% cost, avoids padding to stay under smem cap.
    for (int i = tid; i < H_ * H_; i += 256) {
        int j = i >> 7, k = i & 127;
        sm[SM_W0 + k * H_ + j] = Whh0[i];
        sm[SM_W1 + k * H_ + j] = Wih1[i];
        sm[SM_W2 + k * H_ + j] = Whh1[i];
    }
    for (int i = tid; i < 2 * 32 * H_; i += 256) sm[SM_H0 + i] = 0.0f;

    float bias1[4];
#pragma unroll
    for (int m = 0; m < 4; m++) {
        int j = lane + 32 * m;
        bias1[m] = bih1[j] + bhh1[j];
    }
    __syncthreads();

    const int bloc = warp * 4;                       // warp's first local row
    const int bglob = blockIdx.x * 32 + bloc;
    const float* xw_base = g_xw0 + (size_t)bglob * T_ * H_;

    float* h0 = sm + SM_H0 + bloc * H_;
    float* h1 = sm + SM_H1 + bloc * H_;

    for (int t = 0; t < T_; t++) {
        // ---- layer 0: acc = xw0_t + h0 @ Whh0^T ----
        float acc[4][4];
#pragma unroll
        for (int r = 0; r < 4; r++) {
            const float* p = xw_base + (size_t)(r * T_ + t) * H_;
#pragma unroll
            for (int m = 0; m < 4; m++) acc[m][r] = p[lane + 32 * m];
        }
        matvec_acc4x4(sm + SM_W0, h0, lane, acc);

        float hn[4][4];
#pragma unroll
        for (int m = 0; m < 4; m++)
#pragma unroll
            for (int r = 0; r < 4; r++) hn[m][r] = tanh_fast(acc[m][r]);

        __syncwarp();   // all lanes done reading old h0
#pragma unroll
        for (int r = 0; r < 4; r++)
#pragma unroll
            for (int m = 0; m < 4; m++) h0[r * H_ + lane + 32 * m] = hn[m][r];
        __syncwarp();   // new h0 visible to the warp

        // ---- layer 1: acc = b1 + h0_new @ Wih1^T + h1 @ Whh1^T ----
#pragma unroll
        for (int m = 0; m < 4; m++)
#pragma unroll
            for (int r = 0; r < 4; r++) acc[m][r] = bias1[m];
        matvec_acc4x4(sm + SM_W1, h0, lane, acc);
        matvec_acc4x4(sm + SM_W2, h1, lane, acc);

#pragma unroll
        for (int m = 0; m < 4; m++)
#pragma unroll
            for (int r = 0; r < 4; r++) hn[m][r] = tanh_fast(acc[m][r]);

        __syncwarp();
#pragma unroll
        for (int r = 0; r < 4; r++)
#pragma unroll
            for (int m = 0; m < 4; m++) h1[r * H_ + lane + 32 * m] = hn[m][r];
        __syncwarp();
    }

    // ---- FC: out[b][c] = fc_b[c] + sum_j h1[b][j] * fc_w[c][j] ----
    for (int idx = lane; idx < 4 * C_; idx += 32) {
        int r = idx / C_, c = idx % C_;
        float s = fcb[c];
        const float4* wrow = reinterpret_cast<const float4*>(fcw + c * H_);
        const float4* hrow = reinterpret_cast<const float4*>(h1 + r * H_);
#pragma unroll
        for (int q = 0; q < H_ / 4; q++) {
            float4 w = wrow[q];
            float4 h = hrow[q];
            s += w.x * h.x + w.y * h.y + w.z * h.z + w.w * h.w;
        }
        out[(size_t)(bglob + r) * C_ + c] = s;
    }
}

// ---------------------------------------------------------------------------
extern "C" void kernel_launch(void* const* d_in, const int* in_sizes, int n_in,
                              void* d_out, int out_size)
{
    (void)in_sizes; (void)n_in; (void)out_size;
    const float* x    = (const float*)d_in[0];
    const float* Wih0 = (const float*)d_in[1];
    const float* Whh0 = (const float*)d_in[2];
    const float* bih0 = (const float*)d_in[3];
    const float* bhh0 = (const float*)d_in[4];
    const float* Wih1 = (const float*)d_in[5];
    const float* Whh1 = (const float*)d_in[6];
    const float* bih1 = (const float*)d_in[7];
    const float* bhh1 = (const float*)d_in[8];
    const float* fcw  = (const float*)d_in[9];
    const float* fcb  = (const float*)d_in[10];
    float* out = (float*)d_out;

    xw0_kernel<<<(B_ * T_) / 64, 256>>>(x, Wih0, bih0, bhh0);

    const int smem_bytes = SM_FLOATS * (int)sizeof(float);   // 229376
    cudaFuncSetAttribute(rnn_kernel,
                         cudaFuncAttributeMaxDynamicSharedMemorySize, smem_bytes);
    rnn_kernel<<<B_ / 32, 256, smem_bytes>>>(Whh0, Wih1, Whh1, bih1, bhh1,
                                             fcw, fcb, out);
}

// round 2
// speedup vs baseline: 1.1157x; 1.1157x over previous
#include <cuda_runtime.h>
#include <math.h>

#define H_ 128
#define T_ 28
#define I_ 28
#define C_ 10
#define B_ 8192

typedef unsigned long long u64;

// Global scratch for layer-0 input GEMM results (biases folded in): [B][T][H]
__device__ float g_xw0[(size_t)B_ * T_ * H_];

__device__ __forceinline__ float tanh_fast(float x) {
    // tanh(x) = sign(x) * (1 - e) / (1 + e),  e = exp(-2|x|)
    float ax = fabsf(x);
    float e  = __expf(-2.0f * ax);
    float r  = __fdividef(1.0f - e, 1.0f + e);
    return copysignf(r, x);
}

// ---- packed fp32x2 helpers (Blackwell FFMA2 path, PTX-only) ----
__device__ __forceinline__ void ffma2(u64& d, u64 a, u64 b) {
    asm("fma.rn.f32x2 %0, %1, %2, %0;" : "+l"(d) : "l"(a), "l"(b));
}
__device__ __forceinline__ u64 pack2(float x, float y) {
    u64 r; asm("mov.b64 %0, {%1, %2};" : "=l"(r) : "f"(x), "f"(y)); return r;
}
__device__ __forceinline__ void unpack2(u64 v, float& x, float& y) {
    asm("mov.b64 {%0, %1}, %2;" : "=f"(x), "=f"(y) : "l"(v));
}

// ---------------------------------------------------------------------------
// Kernel 1: xw0[b][t][j] = sum_d x[b][t][d] * W_ih0[j][d] + b_ih0[j] + b_hh0[j]
// Rows = B*T = 229376. Tile: 64 rows x 128 j per block, 256 threads.
// (unchanged from round 1 — ~80us, revisit after rnn kernel is optimized)
// ---------------------------------------------------------------------------
__global__ void __launch_bounds__(256) xw0_kernel(
    const float* __restrict__ x, const float* __restrict__ Wih0,
    const float* __restrict__ bih0, const float* __restrict__ bhh0)
{
    __shared__ float Wt[I_ * 129];   // Wt[d*129 + j] (pad 129 -> conflict-free STS)
    __shared__ float xs[64 * I_];
    __shared__ float bsum[H_];

    const int tid = threadIdx.x, lane = tid & 31, warp = tid >> 5;

    for (int i = tid; i < H_ * I_; i += 256) {
        int j = i / I_, d = i % I_;           // coalesced LDG (i linear)
        Wt[d * 129 + j] = Wih0[i];
    }
    for (int i = tid; i < H_; i += 256) bsum[i] = bih0[i] + bhh0[i];

    const int row0 = blockIdx.x * 64;
    const float* xr = x + (size_t)row0 * I_;
    for (int i = tid; i < 64 * I_; i += 256) xs[i] = xr[i];
    __syncthreads();

    float bj[4];
#pragma unroll
    for (int m = 0; m < 4; m++) bj[m] = bsum[lane + 32 * m];

    float acc[4][8];
#pragma unroll
    for (int m = 0; m < 4; m++)
#pragma unroll
        for (int r = 0; r < 8; r++) acc[m][r] = bj[m];

    const int rbase = warp * 8;
#pragma unroll
    for (int d = 0; d < I_; d++) {
        float w[4];
#pragma unroll
        for (int m = 0; m < 4; m++) w[m] = Wt[d * 129 + lane + 32 * m];
#pragma unroll
        for (int r = 0; r < 8; r++) {
            float xv = xs[(rbase + r) * I_ + d];
#pragma unroll
            for (int m = 0; m < 4; m++) acc[m][r] = fmaf(w[m], xv, acc[m][r]);
        }
    }

    float* outp = g_xw0 + (size_t)(row0 + rbase) * H_;
#pragma unroll
    for (int r = 0; r < 8; r++)
#pragma unroll
        for (int m = 0; m < 4; m++)
            outp[(size_t)r * H_ + lane + 32 * m] = acc[m][r];
}

// ---------------------------------------------------------------------------
// Kernel 2: fused 2-layer recurrence + FC, FFMA2 inner loop.
// 256 CTAs x 256 threads. Warp owns 4 sequences. Thread owns j-pairs
// j = {2p, 2p+1}, p = lane + 32*m2 (m2 = 0,1) -> weight operand is a direct
// conflict-free LDS.64; h broadcast duplicated into both halves via mov.b64.
// ---------------------------------------------------------------------------
#define SM_W0 0
#define SM_W1 (H_ * H_)
#define SM_W2 (2 * H_ * H_)
#define SM_H0 (3 * H_ * H_)
#define SM_H1 (3 * H_ * H_ + 32 * H_)
#define SM_FLOATS (3 * H_ * H_ + 2 * 32 * H_)   // 229376 B

extern __shared__ float sm[];

__device__ __forceinline__ void matvec2(const float* __restrict__ Wt,
                                        const float* __restrict__ h,
                                        int lane, u64 (&acc)[2][4])
{
    const float* w0 = Wt + 2 * lane;        // m2 = 0 pair base
    const float* w1 = Wt + 2 * lane + 64;   // m2 = 1 pair base
#pragma unroll 4
    for (int k4 = 0; k4 < 32; k4++) {
        float4 hv[4];
#pragma unroll
        for (int r = 0; r < 4; r++)
            hv[r] = *reinterpret_cast<const float4*>(h + r * H_ + k4 * 4);
#pragma unroll
        for (int kk = 0; kk < 4; kk++) {
            u64 hp[4];
#pragma unroll
            for (int r = 0; r < 4; r++) {
                float hval = (kk == 0) ? hv[r].x : (kk == 1) ? hv[r].y
                           : (kk == 2) ? hv[r].z : hv[r].w;
                hp[r] = pack2(hval, hval);
            }
            const int k = k4 * 4 + kk;
            u64 wa = *reinterpret_cast<const u64*>(w0 + k * H_);
#pragma unroll
            for (int r = 0; r < 4; r++) ffma2(acc[0][r], wa, hp[r]);
            u64 wb = *reinterpret_cast<const u64*>(w1 + k * H_);
#pragma unroll
            for (int r = 0; r < 4; r++) ffma2(acc[1][r], wb, hp[r]);
        }
    }
}

__global__ void __launch_bounds__(256, 1) rnn_kernel(
    const float* __restrict__ Whh0, const float* __restrict__ Wih1,
    const float* __restrict__ Whh1, const float* __restrict__ bih1,
    const float* __restrict__ bhh1, const float* __restrict__ fcw,
    const float* __restrict__ fcb, float* __restrict__ out)
{
    const int tid = threadIdx.x, lane = tid & 31, warp = tid >> 5;

    // Load weights transposed (k-major). One-time STS conflicts accepted.
    for (int i = tid; i < H_ * H_; i += 256) {
        int j = i >> 7, k = i & 127;
        sm[SM_W0 + k * H_ + j] = Whh0[i];
        sm[SM_W1 + k * H_ + j] = Wih1[i];
        sm[SM_W2 + k * H_ + j] = Whh1[i];
    }
    for (int i = tid; i < 2 * 32 * H_; i += 256) sm[SM_H0 + i] = 0.0f;

    // Packed layer-1 bias: j = {2p, 2p+1}, p = lane + 32*m2
    u64 bias1p[2];
#pragma unroll
    for (int m2 = 0; m2 < 2; m2++) {
        int j = 2 * (lane + 32 * m2);
        bias1p[m2] = pack2(bih1[j] + bhh1[j], bih1[j + 1] + bhh1[j + 1]);
    }
    __syncthreads();

    const int bloc = warp * 4;                       // warp's first local row
    const int bglob = blockIdx.x * 32 + bloc;
    const float* xw_base = g_xw0 + (size_t)bglob * T_ * H_;

    float* h0 = sm + SM_H0 + bloc * H_;
    float* h1 = sm + SM_H1 + bloc * H_;
    const int p0 = 2 * lane;          // float offset of m2=0 pair
    const int p1 = 2 * lane + 64;     // float offset of m2=1 pair

    for (int t = 0; t < T_; t++) {
        // ---- layer 0: acc = xw0_t + h0 @ Whh0^T ----
        u64 acc[2][4];
#pragma unroll
        for (int r = 0; r < 4; r++) {
            const float* pxw = xw_base + (size_t)(r * T_ + t) * H_;
            acc[0][r] = *reinterpret_cast<const u64*>(pxw + p0);
            acc[1][r] = *reinterpret_cast<const u64*>(pxw + p1);
        }
        matvec2(sm + SM_W0, h0, lane, acc);

        __syncwarp();   // all lanes done reading old h0
#pragma unroll
        for (int m2 = 0; m2 < 2; m2++)
#pragma unroll
            for (int r = 0; r < 4; r++) {
                float lo, hi;
                unpack2(acc[m2][r], lo, hi);
                float2 v = make_float2(tanh_fast(lo), tanh_fast(hi));
                *reinterpret_cast<float2*>(h0 + r * H_ + (m2 ? p1 : p0)) = v;
            }
        __syncwarp();   // new h0 visible to the warp

        // ---- layer 1: acc = b1 + h0_new @ Wih1^T + h1 @ Whh1^T ----
#pragma unroll
        for (int m2 = 0; m2 < 2; m2++)
#pragma unroll
            for (int r = 0; r < 4; r++) acc[m2][r] = bias1p[m2];
        matvec2(sm + SM_W1, h0, lane, acc);
        matvec2(sm + SM_W2, h1, lane, acc);

        __syncwarp();
#pragma unroll
        for (int m2 = 0; m2 < 2; m2++)
#pragma unroll
            for (int r = 0; r < 4; r++) {
                float lo, hi;
                unpack2(acc[m2][r], lo, hi);
                float2 v = make_float2(tanh_fast(lo), tanh_fast(hi));
                *reinterpret_cast<float2*>(h1 + r * H_ + (m2 ? p1 : p0)) = v;
            }
        __syncwarp();
    }

    // ---- FC: out[b][c] = fc_b[c] + sum_j h1[b][j] * fc_w[c][j] ----
    for (int idx = lane; idx < 4 * C_; idx += 32) {
        int r = idx / C_, c = idx % C_;
        float s = fcb[c];
        const float4* wrow = reinterpret_cast<const float4*>(fcw + c * H_);
        const float4* hrow = reinterpret_cast<const float4*>(h1 + r * H_);
#pragma unroll
        for (int q = 0; q < H_ / 4; q++) {
            float4 w = wrow[q];
            float4 h = hrow[q];
            s += w.x * h.x + w.y * h.y + w.z * h.z + w.w * h.w;
        }
        out[(size_t)(bglob + r) * C_ + c] = s;
    }
}

// ---------------------------------------------------------------------------
extern "C" void kernel_launch(void* const* d_in, const int* in_sizes, int n_in,
                              void* d_out, int out_size)
{
    (void)in_sizes; (void)n_in; (void)out_size;
    const float* x    = (const float*)d_in[0];
    const float* Wih0 = (const float*)d_in[1];
    const float* Whh0 = (const float*)d_in[2];
    const float* bih0 = (const float*)d_in[3];
    const float* bhh0 = (const float*)d_in[4];
    const float* Wih1 = (const float*)d_in[5];
    const float* Whh1 = (const float*)d_in[6];
    const float* bih1 = (const float*)d_in[7];
    const float* bhh1 = (const float*)d_in[8];
    const float* fcw  = (const float*)d_in[9];
    const float* fcb  = (const float*)d_in[10];
    float* out = (float*)d_out;

    xw0_kernel<<<(B_ * T_) / 64, 256>>>(x, Wih0, bih0, bhh0);

    const int smem_bytes = SM_FLOATS * (int)sizeof(float);   // 229376
    cudaFuncSetAttribute(rnn_kernel,
                         cudaFuncAttributeMaxDynamicSharedMemorySize, smem_bytes);
    rnn_kernel<<<B_ / 32, 256, smem_bytes>>>(Whh0, Wih1, Whh1, bih1, bhh1,
                                             fcw, fcb, out);
}